// round 13
// baseline (speedup 1.0000x reference)
#include <cuda_runtime.h>

// ---- problem constants ----
#define NROWS   8192      // N * OH * OW = 8*32*32
#define IDIM    72        // IC*KH*KW
#define OCH     16
#define NP      5
#define RKU     26        // u64 entries per record: l2, negz*5, alpha'*5, W'*15
#define RECS    60        // smem float stride: og*60%32 distinct -> conflict-free
#define ROWSB   64        // rows per CTA
#define RPT     4         // rows per thread
#define ISPLIT  6
#define IQ      12        // IDIM / ISPLIT

// partial sums: [split][row][og] -> float4(m.lo, m.hi, q.lo, q.hi)
__device__ float4 g_part[ISPLIT * NROWS * 8];

typedef unsigned long long u64;

// ---------------- packed f32x2 + fast-math helpers ----------------
__device__ __forceinline__ u64 pk2(unsigned lo, unsigned hi) {
    u64 d; asm("mov.b64 %0,{%1,%2};" : "=l"(d) : "r"(lo), "r"(hi)); return d;
}
__device__ __forceinline__ void upk(u64 v, unsigned& lo, unsigned& hi) {
    asm("mov.b64 {%0,%1},%2;" : "=r"(lo), "=r"(hi) : "l"(v));
}
__device__ __forceinline__ u64 bc(float f) {
    unsigned u = __float_as_uint(f); return pk2(u, u);
}
__device__ __forceinline__ u64 f2fma(u64 a, u64 b, u64 c) {
    u64 d; asm("fma.rn.f32x2 %0,%1,%2,%3;" : "=l"(d) : "l"(a), "l"(b), "l"(c)); return d;
}
__device__ __forceinline__ u64 f2mul(u64 a, u64 b) {
    u64 d; asm("mul.rn.f32x2 %0,%1,%2;" : "=l"(d) : "l"(a), "l"(b)); return d;
}
__device__ __forceinline__ u64 f2add(u64 a, u64 b) {
    u64 d; asm("add.rn.f32x2 %0,%1,%2;" : "=l"(d) : "l"(a), "l"(b)); return d;
}
__device__ __forceinline__ float ex2f(float x) {
    float y; asm("ex2.approx.f32 %0,%1;" : "=f"(y) : "f"(x)); return y;
}
__device__ __forceinline__ float lg2f(float x) {
    float y; asm("lg2.approx.f32 %0,%1;" : "=f"(y) : "f"(x)); return y;
}
__device__ __forceinline__ float rcpf(float x) {
    float y; asm("rcp.approx.f32 %0,%1;" : "=f"(y) : "f"(x)); return y;
}

// ---------------- fused main: in-CTA Cholesky param solve + GP sweep ----------------
__global__ __launch_bounds__(128, 5) void gp_main(const float* __restrict__ xm,
                                                  const float* __restrict__ xv,
                                                  const float* __restrict__ zg,
                                                  const float* __restrict__ hg,
                                                  const float* __restrict__ raw_l) {
    __shared__ __align__(16) float2 ms_sm[IQ][ROWSB + 1];   // (mu, s2)
    __shared__ __align__(16) float  prm[IQ * 8 * RECS];

    const int tid   = threadIdx.x;
    const int row0  = blockIdx.x * ROWSB;
    const int split = blockIdx.y;
    const int i0    = split * IQ;

    // ---- stage im2col(mu,s2) for this CTA's rows, this split's i-range ----
    for (int idx = tid; idx < IQ * ROWSB; idx += 128) {
        int il = idx >> 6, rlocal = idx & 63;
        int i = i0 + il;
        int c = i / 9, rem = i - c * 9;
        int kh = rem / 3, kw = rem - kh * 3;
        int r = row0 + rlocal;
        int n = r >> 10, oh = (r >> 5) & 31, ow = r & 31;
        int ih = oh + kh - 1, iw = ow + kw - 1;
        float m = 0.0f, v = 0.0f;
        if ((unsigned)ih < 32u && (unsigned)iw < 32u) {
            int g = ((n * 32 + ih) * 32 + iw) * 8 + c;
            m = xm[g]; v = xv[g];
        }
        ms_sm[il][rlocal] = make_float2(m, v);
    }

    // ---- fused per-CTA param solve (proven R6 pipeline, fp32 Cholesky) ----
    for (int t = tid; t < IQ * OCH; t += 128) {
        int il = t >> 4, o = t & 15;
        int i  = i0 + il;
        int oi = o * IDIM + i;

        // softplus via MUFU: sp = ln2 * lg2(1 + 2^(x*log2e))
        float x   = raw_l[oi];
        float tx  = ex2f(x * 1.4426950408889634f);
        float spf = 0.6931471805599453f * lg2f(1.0f + tx);
        float l2f = spf * spf;
        float cK  = -0.7213475204444817f * rcpf(l2f);   // -log2e/(2 l2)

        float zz[NP], hf[NP];
#pragma unroll
        for (int p = 0; p < NP; ++p) {
            zz[p] = zg[oi * NP + p];
            hf[p] = hg[oi * NP + p];
        }

        // K in fp32 via ex2 (validated safe since R6)
        float Kf[NP][NP];
#pragma unroll
        for (int p = 0; p < NP; ++p)
#pragma unroll
            for (int q = 0; q < NP; ++q) {
                float dz = zz[p] - zz[q];
                Kf[p][q] = ex2f(dz * dz * cK) + (p == q ? 1e-4f : 0.0f);
            }

        // fp32 Cholesky K = L L^T (rsqrt + 1 Newton; backward stable)
        float L[NP][NP], rdiag[NP];
#pragma unroll
        for (int j = 0; j < NP; ++j) {
            float s = Kf[j][j];
#pragma unroll
            for (int k = 0; k < NP; ++k) if (k < j) s = fmaf(-L[j][k], L[j][k], s);
            float r = rsqrtf(s);
            r = r * fmaf(-0.5f * s * r, r, 1.5f);
            rdiag[j] = r;
            L[j][j] = s * r;
#pragma unroll
            for (int rr = 0; rr < NP; ++rr) if (rr > j) {
                float tt = Kf[rr][j];
#pragma unroll
                for (int k = 0; k < NP; ++k) if (k < j) tt = fmaf(-L[rr][k], L[j][k], tt);
                L[rr][j] = tt * r;
            }
        }
        // W = L^{-1} (lower): K^{-1} = W^T W
        float W[NP][NP];
#pragma unroll
        for (int j = 0; j < NP; ++j) {
            W[j][j] = rdiag[j];
#pragma unroll
            for (int rr = 0; rr < NP; ++rr) if (rr > j) {
                float tt = 0.0f;
#pragma unroll
                for (int k = 0; k < NP; ++k) if (k >= j && k < rr) tt = fmaf(L[rr][k], W[k][j], tt);
                W[rr][j] = -tt * rdiag[rr];
            }
        }

        // alpha0 = W^T (W h)
        float t1[NP], a0[NP];
#pragma unroll
        for (int p = 0; p < NP; ++p) {
            float s = 0.0f;
#pragma unroll
            for (int q = 0; q < NP; ++q) if (q <= p) s = fmaf(W[p][q], hf[q], s);
            t1[p] = s;
        }
#pragma unroll
        for (int q = 0; q < NP; ++q) {
            float s = 0.0f;
#pragma unroll
            for (int p = 0; p < NP; ++p) if (p >= q) s = fmaf(W[p][q], t1[p], s);
            a0[q] = s;
        }
        // one fp64-residual refinement (Kf promoted inline; cures cond*eps32)
        float rf[NP];
#pragma unroll
        for (int p = 0; p < NP; ++p) {
            double s = (double)hf[p];
#pragma unroll
            for (int q = 0; q < NP; ++q) s = fma(-(double)Kf[p][q], (double)a0[q], s);
            rf[p] = (float)s;
        }
        float t2[NP], al[NP];
#pragma unroll
        for (int p = 0; p < NP; ++p) {
            float s = 0.0f;
#pragma unroll
            for (int q = 0; q < NP; ++q) if (q <= p) s = fmaf(W[p][q], rf[q], s);
            t2[p] = s;
        }
#pragma unroll
        for (int q = 0; q < NP; ++q) {
            float s = a0[q];
#pragma unroll
            for (int p = 0; p < NP; ++p) if (p >= q) s = fmaf(W[p][q], t2[p], s);
            al[q] = s;
        }

        // write record into smem (lane-interleaved): l2, -z*5, (l*alpha)*5, (l*W)*15
        float* rec = &prm[(il * 8 + (o >> 1)) * RECS + (o & 1)];
        rec[0] = l2f;
#pragma unroll
        for (int p = 0; p < NP; ++p) rec[(1 + p) * 2] = -zz[p];
#pragma unroll
        for (int p = 0; p < NP; ++p) rec[(6 + p) * 2] = spf * al[p];
#pragma unroll
        for (int p = 0; p < NP; ++p)
#pragma unroll
            for (int q = 0; q < NP; ++q) if (q <= p)
                rec[(11 + p * (p + 1) / 2 + q) * 2] = spf * W[p][q];
    }
    __syncthreads();

    const int og = tid & 7;          // 8 o-pairs
    const int rp = tid >> 3;         // 16 row-quads -> rows rp*4 .. rp*4+3

    const u64 C_NHL2E = bc(-0.7213475204444817f);   // -0.5*log2(e)

    u64 macc[RPT] = {0ULL, 0ULL, 0ULL, 0ULL};
    u64 qacc[RPT] = {0ULL, 0ULL, 0ULL, 0ULL};

    for (int il = 0; il < IQ; ++il) {
        // record -> registers once, reused for RPT rows
        const uint4* Rq = reinterpret_cast<const uint4*>(&prm[(il * 8 + og) * RECS]);
        u64 P[RKU];
#pragma unroll
        for (int k4 = 0; k4 < 13; ++k4) {
            uint4 q = Rq[k4];
            P[2 * k4]     = pk2(q.x, q.y);
            P[2 * k4 + 1] = pk2(q.z, q.w);
        }
        const u64 l2 = P[0];

#pragma unroll
        for (int rr = 0; rr < RPT; ++rr) {
            const float2 msv = ms_sm[il][rp * RPT + rr];
            const u64 MU = bc(msv.x);
            const u64 S2 = bc(msv.y);

            // d = l2 + s2; r = 1/sqrt(d) via MUFU per half
            u64 d = f2add(l2, S2);
            unsigned dlo, dhi; upk(d, dlo, dhi);
            float rlo = rsqrtf(__uint_as_float(dlo));
            float rhi = rsqrtf(__uint_as_float(dhi));
            u64 r   = pk2(__float_as_uint(rlo), __float_as_uint(rhi));
            u64 rsq = f2mul(r, r);                   // 1/d
            const u64 ccp = f2mul(rsq, C_NHL2E);     // -log2e/(2d)

            // e_p = 2^( ccp*(mu-z_p)^2 ) via MUFU EX2 per half
            u64 e[NP];
#pragma unroll
            for (int p = 0; p < NP; ++p) {
                u64 t  = f2add(MU, P[1 + p]);        // P holds -z
                u64 t2 = f2mul(t, t);
                u64 y  = f2mul(t2, ccp);
                unsigned ylo, yhi; upk(y, ylo, yhi);
                float elo = ex2f(__uint_as_float(ylo));
                float ehi = ex2f(__uint_as_float(yhi));
                e[p] = pk2(__float_as_uint(elo), __float_as_uint(ehi));
            }

            // l*mean: e . alpha'  (alpha' = l*alpha at P[6..10])
            u64 me = f2mul(e[0], P[6]);
            me = f2fma(e[1], P[7],  me);
            me = f2fma(e[2], P[8],  me);
            me = f2fma(e[3], P[9],  me);
            me = f2fma(e[4], P[10], me);

            // l2*qKq = ||W' e||^2  (W' = l*W lower-tri at P[11..25])
            u64 v0 = f2mul(P[11], e[0]);
            u64 v1 = f2fma(P[13], e[1], f2mul(P[12], e[0]));
            u64 v2 = f2fma(P[16], e[2], f2fma(P[15], e[1], f2mul(P[14], e[0])));
            u64 v3 = f2fma(P[20], e[3], f2fma(P[19], e[2],
                     f2fma(P[18], e[1], f2mul(P[17], e[0]))));
            u64 v4 = f2fma(P[25], e[4], f2fma(P[24], e[3],
                     f2fma(P[23], e[2], f2fma(P[22], e[1], f2mul(P[21], e[0])))));
            u64 qk = f2mul(v0, v0);
            qk = f2fma(v1, v1, qk);
            qk = f2fma(v2, v2, qk);
            qk = f2fma(v3, v3, qk);
            qk = f2fma(v4, v4, qk);

            macc[rr] = f2fma(me, r,   macc[rr]);   // s*mean = r * (l*mean)
            qacc[rr] = f2fma(qk, rsq, qacc[rr]);   // (1/d) * (l2*qKq)
        }
    }

#pragma unroll
    for (int rr = 0; rr < RPT; ++rr) {
        const int r = row0 + rp * RPT + rr;
        unsigned mlo, mhi, qlo, qhi;
        upk(macc[rr], mlo, mhi); upk(qacc[rr], qlo, qhi);
        g_part[(split * NROWS + r) * 8 + og] =
            make_float4(__uint_as_float(mlo), __uint_as_float(mhi),
                        __uint_as_float(qlo), __uint_as_float(qhi));
    }
}

// ---------------- reduce: combine the 6 i-splits ----------------
__global__ __launch_bounds__(256) void gp_reduce(float* __restrict__ out) {
    int idx = blockIdx.x * 256 + threadIdx.x;       // over NROWS*8
    if (idx >= NROWS * 8) return;
    float4 a0 = g_part[idx];
    float4 a1 = g_part[NROWS * 8 + idx];
    float4 a2 = g_part[2 * NROWS * 8 + idx];
    float4 a3 = g_part[3 * NROWS * 8 + idx];
    float4 a4 = g_part[4 * NROWS * 8 + idx];
    float4 a5 = g_part[5 * NROWS * 8 + idx];
    float mx = ((a0.x + a1.x) + (a2.x + a3.x)) + (a4.x + a5.x);
    float my = ((a0.y + a1.y) + (a2.y + a3.y)) + (a4.y + a5.y);
    float qz = ((a0.z + a1.z) + (a2.z + a3.z)) + (a4.z + a5.z);
    float qw = ((a0.w + a1.w) + (a2.w + a3.w)) + (a4.w + a5.w);
    reinterpret_cast<float2*>(out)[idx] = make_float2(mx, my);
    reinterpret_cast<float2*>(out + NROWS * OCH)[idx] =
        make_float2(fmaxf(72.0f - qz, 1e-6f), fmaxf(72.0f - qw, 1e-6f));
}

extern "C" void kernel_launch(void* const* d_in, const int* in_sizes, int n_in,
                              void* d_out, int out_size) {
    const float* xm  = (const float*)d_in[0];  // x_mean [8,32,32,8]
    const float* xv  = (const float*)d_in[1];  // x_var
    const float* z   = (const float*)d_in[2];  // [16,72,5]
    const float* h   = (const float*)d_in[3];  // [16,72,5]
    const float* rlp = (const float*)d_in[4];  // [16,72]
    float* out = (float*)d_out;                // [m (131072) | v (131072)]

    gp_main<<<dim3(NROWS / ROWSB, ISPLIT), 128>>>(xm, xv, z, h, rlp);
    gp_reduce<<<NROWS * 8 / 256, 256>>>(out);
}

// round 14
// speedup vs baseline: 1.1404x; 1.1404x over previous
#include <cuda_runtime.h>

// ---- problem constants ----
#define NROWS   8192      // N * OH * OW = 8*32*32
#define IDIM    72        // IC*KH*KW
#define OCH     16
#define NP      5
#define RKU     26        // u64 entries per record: l2, negz*5, alpha'*5, W'*15
#define RECF    52        // floats per record in global (= RKU*2) = 13 uint4
#define RECS    60        // smem float stride: og*60%32 distinct -> conflict-free
#define ROWSB   64        // rows per CTA
#define RPT     4         // rows per thread
#define ISPLIT  6
#define IQ      12        // IDIM / ISPLIT
#define NBX     (NROWS / ROWSB)   // 128

// global param table: [i][og][RECF] floats, og = o>>1, float2-interleaved over lane=o&1
__device__ float g_params[IDIM * 8 * RECF];
// partial sums: [split][row][og] -> float4(m.lo, m.hi, q.lo, q.hi)
__device__ float4 g_part[ISPLIT * NROWS * 8];
// per-rowblock arrival counters (zero-init; finalizer resets -> replay-safe)
__device__ unsigned g_cnt[NBX];

typedef unsigned long long u64;

// ---------------- packed f32x2 + fast-math helpers ----------------
__device__ __forceinline__ u64 pk2(unsigned lo, unsigned hi) {
    u64 d; asm("mov.b64 %0,{%1,%2};" : "=l"(d) : "r"(lo), "r"(hi)); return d;
}
__device__ __forceinline__ void upk(u64 v, unsigned& lo, unsigned& hi) {
    asm("mov.b64 {%0,%1},%2;" : "=r"(lo), "=r"(hi) : "l"(v));
}
__device__ __forceinline__ u64 bc(float f) {
    unsigned u = __float_as_uint(f); return pk2(u, u);
}
__device__ __forceinline__ u64 f2fma(u64 a, u64 b, u64 c) {
    u64 d; asm("fma.rn.f32x2 %0,%1,%2,%3;" : "=l"(d) : "l"(a), "l"(b), "l"(c)); return d;
}
__device__ __forceinline__ u64 f2mul(u64 a, u64 b) {
    u64 d; asm("mul.rn.f32x2 %0,%1,%2;" : "=l"(d) : "l"(a), "l"(b)); return d;
}
__device__ __forceinline__ u64 f2add(u64 a, u64 b) {
    u64 d; asm("add.rn.f32x2 %0,%1,%2;" : "=l"(d) : "l"(a), "l"(b)); return d;
}
__device__ __forceinline__ float ex2f(float x) {
    float y; asm("ex2.approx.f32 %0,%1;" : "=f"(y) : "f"(x)); return y;
}
__device__ __forceinline__ float lg2f(float x) {
    float y; asm("lg2.approx.f32 %0,%1;" : "=f"(y) : "f"(x)); return y;
}
__device__ __forceinline__ float rcpf(float x) {
    float y; asm("rcp.approx.f32 %0,%1;" : "=f"(y) : "f"(x)); return y;
}

// ---------------- precompute: fp32 Cholesky + fp64-residual refinement (R9 proven) ----------------
__global__ void gp_pre(const float* __restrict__ z,
                       const float* __restrict__ h,
                       const float* __restrict__ raw_l) {
    int pid = blockIdx.x * blockDim.x + threadIdx.x;
    if (pid >= IDIM * OCH) return;
    int o = pid / IDIM, i = pid - o * IDIM;
    int oi = o * IDIM + i;

    // softplus via MUFU: sp = ln2 * lg2(1 + 2^(x*log2e))
    float x   = raw_l[oi];
    float tx  = ex2f(x * 1.4426950408889634f);
    float spf = 0.6931471805599453f * lg2f(1.0f + tx);
    float l2f = spf * spf;
    float cK  = -0.7213475204444817f * rcpf(l2f);   // -log2e/(2 l2)

    float zz[NP], hf[NP];
#pragma unroll
    for (int p = 0; p < NP; ++p) {
        zz[p] = z[oi * NP + p];
        hf[p] = h[oi * NP + p];
    }

    // K in fp32 via ex2 (validated safe); fp64 copy for alpha refinement
    float  Kf[NP][NP];
    double Kd[NP][NP];
#pragma unroll
    for (int p = 0; p < NP; ++p)
#pragma unroll
        for (int q = 0; q < NP; ++q) {
            float dz = zz[p] - zz[q];
            float v = ex2f(dz * dz * cK) + (p == q ? 1e-4f : 0.0f);
            Kf[p][q] = v; Kd[p][q] = (double)v;
        }

    // fp32 Cholesky K = L L^T (rsqrt + 1 Newton)
    float L[NP][NP], rdiag[NP];
#pragma unroll
    for (int j = 0; j < NP; ++j) {
        float s = Kf[j][j];
#pragma unroll
        for (int k = 0; k < NP; ++k) if (k < j) s = fmaf(-L[j][k], L[j][k], s);
        float r = rsqrtf(s);
        r = r * fmaf(-0.5f * s * r, r, 1.5f);
        rdiag[j] = r;
        L[j][j] = s * r;
#pragma unroll
        for (int rr = 0; rr < NP; ++rr) if (rr > j) {
            float t = Kf[rr][j];
#pragma unroll
            for (int k = 0; k < NP; ++k) if (k < j) t = fmaf(-L[rr][k], L[j][k], t);
            L[rr][j] = t * r;
        }
    }
    // W = L^{-1} (lower): K^{-1} = W^T W
    float W[NP][NP];
#pragma unroll
    for (int j = 0; j < NP; ++j) {
        W[j][j] = rdiag[j];
#pragma unroll
        for (int rr = 0; rr < NP; ++rr) if (rr > j) {
            float t = 0.0f;
#pragma unroll
            for (int k = 0; k < NP; ++k) if (k >= j && k < rr) t = fmaf(L[rr][k], W[k][j], t);
            W[rr][j] = -t * rdiag[rr];
        }
    }

    // alpha0 = W^T (W h), one fp64-residual refinement
    float t1[NP], a0[NP];
#pragma unroll
    for (int p = 0; p < NP; ++p) {
        float s = 0.0f;
#pragma unroll
        for (int q = 0; q < NP; ++q) if (q <= p) s = fmaf(W[p][q], hf[q], s);
        t1[p] = s;
    }
#pragma unroll
    for (int q = 0; q < NP; ++q) {
        float s = 0.0f;
#pragma unroll
        for (int p = 0; p < NP; ++p) if (p >= q) s = fmaf(W[p][q], t1[p], s);
        a0[q] = s;
    }
    float rf[NP];
#pragma unroll
    for (int p = 0; p < NP; ++p) {
        double s = (double)hf[p];
#pragma unroll
        for (int q = 0; q < NP; ++q) s = fma(-Kd[p][q], (double)a0[q], s);
        rf[p] = (float)s;
    }
    float t2[NP], al[NP];
#pragma unroll
    for (int p = 0; p < NP; ++p) {
        float s = 0.0f;
#pragma unroll
        for (int q = 0; q < NP; ++q) if (q <= p) s = fmaf(W[p][q], rf[q], s);
        t2[p] = s;
    }
#pragma unroll
    for (int q = 0; q < NP; ++q) {
        float s = a0[q];
#pragma unroll
        for (int p = 0; p < NP; ++p) if (p >= q) s = fmaf(W[p][q], t2[p], s);
        al[q] = s;
    }

    // record (float2-interleaved): l2, -z*5, (l*alpha)*5, (l*W)*15
    int og = o >> 1, lane = o & 1;
    float* rec = g_params + (i * 8 + og) * RECF + lane;
    rec[0] = l2f;
#pragma unroll
    for (int p = 0; p < NP; ++p) rec[(1 + p) * 2] = -zz[p];
#pragma unroll
    for (int p = 0; p < NP; ++p) rec[(6 + p) * 2] = spf * al[p];
#pragma unroll
    for (int p = 0; p < NP; ++p)
#pragma unroll
        for (int q = 0; q < NP; ++q) if (q <= p)
            rec[(11 + p * (p + 1) / 2 + q) * 2] = spf * W[p][q];
}

// ---------------- main: 6-way i-split + last-CTA finalize (no reduce kernel) ----------------
__global__ __launch_bounds__(128) void gp_main(const float* __restrict__ xm,
                                               const float* __restrict__ xv,
                                               float* __restrict__ out) {
    __shared__ __align__(16) float2 ms_sm[IQ][ROWSB + 1];   // (mu, s2)
    __shared__ __align__(16) float  prm[IQ * 8 * RECS];
    __shared__ unsigned s_last;

    const int tid   = threadIdx.x;
    const int row0  = blockIdx.x * ROWSB;
    const int split = blockIdx.y;
    const int i0    = split * IQ;

    // stage im2col(mu,s2) for this CTA's rows, this split's i-range
    for (int idx = tid; idx < IQ * ROWSB; idx += 128) {
        int il = idx >> 6, rlocal = idx & 63;
        int i = i0 + il;
        int c = i / 9, rem = i - c * 9;
        int kh = rem / 3, kw = rem - kh * 3;
        int r = row0 + rlocal;
        int n = r >> 10, oh = (r >> 5) & 31, ow = r & 31;
        int ih = oh + kh - 1, iw = ow + kw - 1;
        float m = 0.0f, v = 0.0f;
        if ((unsigned)ih < 32u && (unsigned)iw < 32u) {
            int g = ((n * 32 + ih) * 32 + iw) * 8 + c;
            m = xm[g]; v = xv[g];
        }
        ms_sm[il][rlocal] = make_float2(m, v);
    }
    // stage this split's param records: IQ x 8 x 13 uint4, contiguous in global
    {
        const uint4* src = reinterpret_cast<const uint4*>(g_params + i0 * 8 * RECF);
        for (int idx = tid; idx < IQ * 8 * 13; idx += 128) {
            int rrec = idx / 13, k4 = idx - rrec * 13;
            uint4 v4 = src[idx];
            *reinterpret_cast<uint4*>(&prm[rrec * RECS + 4 * k4]) = v4;
        }
    }
    __syncthreads();

    const int og = tid & 7;          // 8 o-pairs
    const int rp = tid >> 3;         // 16 row-quads -> rows rp*4 .. rp*4+3

    const u64 C_NHL2E = bc(-0.7213475204444817f);   // -0.5*log2(e)

    u64 macc[RPT] = {0ULL, 0ULL, 0ULL, 0ULL};
    u64 qacc[RPT] = {0ULL, 0ULL, 0ULL, 0ULL};

    for (int il = 0; il < IQ; ++il) {
        // record -> registers once, reused for RPT rows
        const uint4* Rq = reinterpret_cast<const uint4*>(&prm[(il * 8 + og) * RECS]);
        u64 P[RKU];
#pragma unroll
        for (int k4 = 0; k4 < 13; ++k4) {
            uint4 q = Rq[k4];
            P[2 * k4]     = pk2(q.x, q.y);
            P[2 * k4 + 1] = pk2(q.z, q.w);
        }
        const u64 l2 = P[0];

#pragma unroll
        for (int rr = 0; rr < RPT; ++rr) {
            const float2 msv = ms_sm[il][rp * RPT + rr];
            const u64 MU = bc(msv.x);
            const u64 S2 = bc(msv.y);

            // d = l2 + s2; r = 1/sqrt(d) via MUFU per half
            u64 d = f2add(l2, S2);
            unsigned dlo, dhi; upk(d, dlo, dhi);
            float rlo = rsqrtf(__uint_as_float(dlo));
            float rhi = rsqrtf(__uint_as_float(dhi));
            u64 r   = pk2(__float_as_uint(rlo), __float_as_uint(rhi));
            u64 rsq = f2mul(r, r);                   // 1/d
            const u64 ccp = f2mul(rsq, C_NHL2E);     // -log2e/(2d)

            // e_p = 2^( ccp*(mu-z_p)^2 ) via MUFU EX2 per half
            u64 e[NP];
#pragma unroll
            for (int p = 0; p < NP; ++p) {
                u64 t  = f2add(MU, P[1 + p]);        // P holds -z
                u64 t2 = f2mul(t, t);
                u64 y  = f2mul(t2, ccp);
                unsigned ylo, yhi; upk(y, ylo, yhi);
                float elo = ex2f(__uint_as_float(ylo));
                float ehi = ex2f(__uint_as_float(yhi));
                e[p] = pk2(__float_as_uint(elo), __float_as_uint(ehi));
            }

            // l*mean: e . alpha'  (alpha' = l*alpha at P[6..10])
            u64 me = f2mul(e[0], P[6]);
            me = f2fma(e[1], P[7],  me);
            me = f2fma(e[2], P[8],  me);
            me = f2fma(e[3], P[9],  me);
            me = f2fma(e[4], P[10], me);

            // l2*qKq = ||W' e||^2  (W' = l*W lower-tri at P[11..25])
            u64 v0 = f2mul(P[11], e[0]);
            u64 v1 = f2fma(P[13], e[1], f2mul(P[12], e[0]));
            u64 v2 = f2fma(P[16], e[2], f2fma(P[15], e[1], f2mul(P[14], e[0])));
            u64 v3 = f2fma(P[20], e[3], f2fma(P[19], e[2],
                     f2fma(P[18], e[1], f2mul(P[17], e[0]))));
            u64 v4 = f2fma(P[25], e[4], f2fma(P[24], e[3],
                     f2fma(P[23], e[2], f2fma(P[22], e[1], f2mul(P[21], e[0])))));
            u64 qk = f2mul(v0, v0);
            qk = f2fma(v1, v1, qk);
            qk = f2fma(v2, v2, qk);
            qk = f2fma(v3, v3, qk);
            qk = f2fma(v4, v4, qk);

            macc[rr] = f2fma(me, r,   macc[rr]);   // s*mean = r * (l*mean)
            qacc[rr] = f2fma(qk, rsq, qacc[rr]);   // (1/d) * (l2*qKq)
        }
    }

    // ---- store partials ----
#pragma unroll
    for (int rr = 0; rr < RPT; ++rr) {
        const int r = row0 + rp * RPT + rr;
        unsigned mlo, mhi, qlo, qhi;
        upk(macc[rr], mlo, mhi); upk(qacc[rr], qlo, qhi);
        g_part[(split * NROWS + r) * 8 + og] =
            make_float4(__uint_as_float(mlo), __uint_as_float(mhi),
                        __uint_as_float(qlo), __uint_as_float(qhi));
    }

    // ---- last-CTA-per-rowblock finalize ----
    __threadfence();
    if (tid == 0) {
        unsigned v = atomicAdd(&g_cnt[blockIdx.x], 1u);
        s_last = (v == ISPLIT - 1) ? 1u : 0u;
    }
    __syncthreads();
    if (s_last) {
        __threadfence();    // acquire: make other splits' g_part stores visible
        for (int idx = tid; idx < ROWSB * 8; idx += 128) {
            int base = (row0 + (idx >> 3)) * 8 + (idx & 7);
            float4 a0 = g_part[base];
            float4 a1 = g_part[NROWS * 8 + base];
            float4 a2 = g_part[2 * NROWS * 8 + base];
            float4 a3 = g_part[3 * NROWS * 8 + base];
            float4 a4 = g_part[4 * NROWS * 8 + base];
            float4 a5 = g_part[5 * NROWS * 8 + base];
            float mx = ((a0.x + a1.x) + (a2.x + a3.x)) + (a4.x + a5.x);
            float my = ((a0.y + a1.y) + (a2.y + a3.y)) + (a4.y + a5.y);
            float qz = ((a0.z + a1.z) + (a2.z + a3.z)) + (a4.z + a5.z);
            float qw = ((a0.w + a1.w) + (a2.w + a3.w)) + (a4.w + a5.w);
            reinterpret_cast<float2*>(out)[base] = make_float2(mx, my);
            reinterpret_cast<float2*>(out + NROWS * OCH)[base] =
                make_float2(fmaxf(72.0f - qz, 1e-6f), fmaxf(72.0f - qw, 1e-6f));
        }
        __syncthreads();
        if (tid == 0) g_cnt[blockIdx.x] = 0;   // reset for next graph replay
    }
}

extern "C" void kernel_launch(void* const* d_in, const int* in_sizes, int n_in,
                              void* d_out, int out_size) {
    const float* xm  = (const float*)d_in[0];  // x_mean [8,32,32,8]
    const float* xv  = (const float*)d_in[1];  // x_var
    const float* z   = (const float*)d_in[2];  // [16,72,5]
    const float* h   = (const float*)d_in[3];  // [16,72,5]
    const float* rlp = (const float*)d_in[4];  // [16,72]
    float* out = (float*)d_out;                // [m (131072) | v (131072)]

    gp_pre<<<36, 32>>>(z, h, rlp);
    gp_main<<<dim3(NBX, ISPLIT), 128>>>(xm, xv, out);
}

// round 15
// speedup vs baseline: 1.2448x; 1.0915x over previous
#include <cuda_runtime.h>

// ---- problem constants ----
#define NROWS   8192      // N * OH * OW = 8*32*32
#define IDIM    72        // IC*KH*KW
#define OCH     16
#define NP      5
#define RECF    52        // floats per record in global = 13 uint4
#define RECS    60        // smem float stride: og*60%32 distinct -> conflict-free
#define ROWSB   64        // rows per CTA
#define RPT     4         // rows per thread
#define ISPLIT  6
#define IQ      12        // IDIM / ISPLIT

// global param table: [i][og][RECF] floats, og = o>>1, float2-interleaved over lane=o&1
__device__ float g_params[IDIM * 8 * RECF];
// partial sums: [split][row][og] -> float4(m.lo, m.hi, q.lo, q.hi)
__device__ float4 g_part[ISPLIT * NROWS * 8];

typedef unsigned long long u64;

// ---------------- packed f32x2 + fast-math helpers ----------------
__device__ __forceinline__ u64 pk2(unsigned lo, unsigned hi) {
    u64 d; asm("mov.b64 %0,{%1,%2};" : "=l"(d) : "r"(lo), "r"(hi)); return d;
}
__device__ __forceinline__ void upk(u64 v, unsigned& lo, unsigned& hi) {
    asm("mov.b64 {%0,%1},%2;" : "=r"(lo), "=r"(hi) : "l"(v));
}
__device__ __forceinline__ u64 bc(float f) {
    unsigned u = __float_as_uint(f); return pk2(u, u);
}
__device__ __forceinline__ u64 f2fma(u64 a, u64 b, u64 c) {
    u64 d; asm("fma.rn.f32x2 %0,%1,%2,%3;" : "=l"(d) : "l"(a), "l"(b), "l"(c)); return d;
}
__device__ __forceinline__ u64 f2mul(u64 a, u64 b) {
    u64 d; asm("mul.rn.f32x2 %0,%1,%2;" : "=l"(d) : "l"(a), "l"(b)); return d;
}
__device__ __forceinline__ u64 f2add(u64 a, u64 b) {
    u64 d; asm("add.rn.f32x2 %0,%1,%2;" : "=l"(d) : "l"(a), "l"(b)); return d;
}
__device__ __forceinline__ float ex2f(float x) {
    float y; asm("ex2.approx.f32 %0,%1;" : "=f"(y) : "f"(x)); return y;
}
__device__ __forceinline__ float lg2f(float x) {
    float y; asm("lg2.approx.f32 %0,%1;" : "=f"(y) : "f"(x)); return y;
}
__device__ __forceinline__ float rcpf(float x) {
    float y; asm("rcp.approx.f32 %0,%1;" : "=f"(y) : "f"(x)); return y;
}
// volatile smem b64 load: NOT hoistable/CSE-able -> keeps W out of registers
__device__ __forceinline__ u64 lds64v(unsigned addr) {
    u64 r; asm volatile("ld.shared.b64 %0,[%1];" : "=l"(r) : "r"(addr)); return r;
}

// ---------------- precompute: fp32 Cholesky + fp64-residual refinement (R9 proven) ----------------
__global__ void gp_pre(const float* __restrict__ z,
                       const float* __restrict__ h,
                       const float* __restrict__ raw_l) {
    int pid = blockIdx.x * blockDim.x + threadIdx.x;
    if (pid >= IDIM * OCH) return;
    int o = pid / IDIM, i = pid - o * IDIM;
    int oi = o * IDIM + i;

    // softplus via MUFU: sp = ln2 * lg2(1 + 2^(x*log2e))
    float x   = raw_l[oi];
    float tx  = ex2f(x * 1.4426950408889634f);
    float spf = 0.6931471805599453f * lg2f(1.0f + tx);
    float l2f = spf * spf;
    float cK  = -0.7213475204444817f * rcpf(l2f);   // -log2e/(2 l2)

    float zz[NP], hf[NP];
#pragma unroll
    for (int p = 0; p < NP; ++p) {
        zz[p] = z[oi * NP + p];
        hf[p] = h[oi * NP + p];
    }

    // K in fp32 via ex2 (validated safe); fp64 copy for alpha refinement
    float  Kf[NP][NP];
    double Kd[NP][NP];
#pragma unroll
    for (int p = 0; p < NP; ++p)
#pragma unroll
        for (int q = 0; q < NP; ++q) {
            float dz = zz[p] - zz[q];
            float v = ex2f(dz * dz * cK) + (p == q ? 1e-4f : 0.0f);
            Kf[p][q] = v; Kd[p][q] = (double)v;
        }

    // fp32 Cholesky K = L L^T (rsqrt + 1 Newton)
    float L[NP][NP], rdiag[NP];
#pragma unroll
    for (int j = 0; j < NP; ++j) {
        float s = Kf[j][j];
#pragma unroll
        for (int k = 0; k < NP; ++k) if (k < j) s = fmaf(-L[j][k], L[j][k], s);
        float r = rsqrtf(s);
        r = r * fmaf(-0.5f * s * r, r, 1.5f);
        rdiag[j] = r;
        L[j][j] = s * r;
#pragma unroll
        for (int rr = 0; rr < NP; ++rr) if (rr > j) {
            float t = Kf[rr][j];
#pragma unroll
            for (int k = 0; k < NP; ++k) if (k < j) t = fmaf(-L[rr][k], L[j][k], t);
            L[rr][j] = t * r;
        }
    }
    // W = L^{-1} (lower): K^{-1} = W^T W
    float W[NP][NP];
#pragma unroll
    for (int j = 0; j < NP; ++j) {
        W[j][j] = rdiag[j];
#pragma unroll
        for (int rr = 0; rr < NP; ++rr) if (rr > j) {
            float t = 0.0f;
#pragma unroll
            for (int k = 0; k < NP; ++k) if (k >= j && k < rr) t = fmaf(L[rr][k], W[k][j], t);
            W[rr][j] = -t * rdiag[rr];
        }
    }

    // alpha0 = W^T (W h), one fp64-residual refinement
    float t1[NP], a0[NP];
#pragma unroll
    for (int p = 0; p < NP; ++p) {
        float s = 0.0f;
#pragma unroll
        for (int q = 0; q < NP; ++q) if (q <= p) s = fmaf(W[p][q], hf[q], s);
        t1[p] = s;
    }
#pragma unroll
    for (int q = 0; q < NP; ++q) {
        float s = 0.0f;
#pragma unroll
        for (int p = 0; p < NP; ++p) if (p >= q) s = fmaf(W[p][q], t1[p], s);
        a0[q] = s;
    }
    float rf[NP];
#pragma unroll
    for (int p = 0; p < NP; ++p) {
        double s = (double)hf[p];
#pragma unroll
        for (int q = 0; q < NP; ++q) s = fma(-Kd[p][q], (double)a0[q], s);
        rf[p] = (float)s;
    }
    float t2[NP], al[NP];
#pragma unroll
    for (int p = 0; p < NP; ++p) {
        float s = 0.0f;
#pragma unroll
        for (int q = 0; q < NP; ++q) if (q <= p) s = fmaf(W[p][q], rf[q], s);
        t2[p] = s;
    }
#pragma unroll
    for (int q = 0; q < NP; ++q) {
        float s = a0[q];
#pragma unroll
        for (int p = 0; p < NP; ++p) if (p >= q) s = fmaf(W[p][q], t2[p], s);
        al[q] = s;
    }

    // record (float2-interleaved): l2, -z*5, (l*alpha)*5, (l*W)*15
    int og = o >> 1, lane = o & 1;
    float* rec = g_params + (i * 8 + og) * RECF + lane;
    rec[0] = l2f;
#pragma unroll
    for (int p = 0; p < NP; ++p) rec[(1 + p) * 2] = -zz[p];
#pragma unroll
    for (int p = 0; p < NP; ++p) rec[(6 + p) * 2] = spf * al[p];
#pragma unroll
    for (int p = 0; p < NP; ++p)
#pragma unroll
        for (int q = 0; q < NP; ++q) if (q <= p)
            rec[(11 + p * (p + 1) / 2 + q) * 2] = spf * W[p][q];
}

// ---------------- main: 6-way i-split, W streamed from smem (low regs) ----------------
__global__ __launch_bounds__(128, 6) void gp_main(const float* __restrict__ xm,
                                                  const float* __restrict__ xv) {
    __shared__ __align__(16) float2 ms_sm[IQ][ROWSB + 1];   // (mu, s2)
    __shared__ __align__(16) float  prm[IQ * 8 * RECS];

    const int tid   = threadIdx.x;
    const int row0  = blockIdx.x * ROWSB;
    const int split = blockIdx.y;
    const int i0    = split * IQ;

    // stage im2col(mu,s2) for this CTA's rows, this split's i-range
    for (int idx = tid; idx < IQ * ROWSB; idx += 128) {
        int il = idx >> 6, rlocal = idx & 63;
        int i = i0 + il;
        int c = i / 9, rem = i - c * 9;
        int kh = rem / 3, kw = rem - kh * 3;
        int r = row0 + rlocal;
        int n = r >> 10, oh = (r >> 5) & 31, ow = r & 31;
        int ih = oh + kh - 1, iw = ow + kw - 1;
        float m = 0.0f, v = 0.0f;
        if ((unsigned)ih < 32u && (unsigned)iw < 32u) {
            int g = ((n * 32 + ih) * 32 + iw) * 8 + c;
            m = xm[g]; v = xv[g];
        }
        ms_sm[il][rlocal] = make_float2(m, v);
    }
    // stage this split's param records: IQ x 8 x 13 uint4, contiguous in global
    {
        const uint4* src = reinterpret_cast<const uint4*>(g_params + i0 * 8 * RECF);
        for (int idx = tid; idx < IQ * 8 * 13; idx += 128) {
            int rrec = idx / 13, k4 = idx - rrec * 13;
            uint4 v4 = src[idx];
            *reinterpret_cast<uint4*>(&prm[rrec * RECS + 4 * k4]) = v4;
        }
    }
    __syncthreads();

    const int og = tid & 7;          // 8 o-pairs
    const int rp = tid >> 3;         // 16 row-quads -> rows rp*4 .. rp*4+3

    const u64 C_NHL2E = bc(-0.7213475204444817f);   // -0.5*log2(e)

    u64 macc[RPT] = {0ULL, 0ULL, 0ULL, 0ULL};
    u64 qacc[RPT] = {0ULL, 0ULL, 0ULL, 0ULL};

    for (int il = 0; il < IQ; ++il) {
        const float* recf = &prm[(il * 8 + og) * RECS];
        const unsigned wb = (unsigned)__cvta_generic_to_shared(recf);

        // preload only l2, -z*5, alpha'*5 (entries 0..10 -> 22 regs)
        u64 P[11];
        {
            const uint4* Rq = reinterpret_cast<const uint4*>(recf);
#pragma unroll
            for (int k4 = 0; k4 < 5; ++k4) {
                uint4 q = Rq[k4];
                P[2 * k4]     = pk2(q.x, q.y);
                if (k4 < 5) P[2 * k4 + 1] = pk2(q.z, q.w);
            }
            P[10] = *reinterpret_cast<const u64*>(recf + 20);
        }
        const u64 l2 = P[0];

        // W' entry k (k=0..14 -> record entry 11+k) streamed per use
#define LW(k) lds64v(wb + (11 + (k)) * 8)

#pragma unroll
        for (int rr = 0; rr < RPT; ++rr) {
            const float2 msv = ms_sm[il][rp * RPT + rr];
            const u64 MU = bc(msv.x);
            const u64 S2 = bc(msv.y);

            // d = l2 + s2; r = 1/sqrt(d) via MUFU per half
            u64 d = f2add(l2, S2);
            unsigned dlo, dhi; upk(d, dlo, dhi);
            float rlo = rsqrtf(__uint_as_float(dlo));
            float rhi = rsqrtf(__uint_as_float(dhi));
            u64 r   = pk2(__float_as_uint(rlo), __float_as_uint(rhi));
            u64 rsq = f2mul(r, r);                   // 1/d
            const u64 ccp = f2mul(rsq, C_NHL2E);     // -log2e/(2d)

            // e_p = 2^( ccp*(mu-z_p)^2 ) via MUFU EX2 per half
            u64 e[NP];
#pragma unroll
            for (int p = 0; p < NP; ++p) {
                u64 t  = f2add(MU, P[1 + p]);        // P holds -z
                u64 t2 = f2mul(t, t);
                u64 y  = f2mul(t2, ccp);
                unsigned ylo, yhi; upk(y, ylo, yhi);
                float elo = ex2f(__uint_as_float(ylo));
                float ehi = ex2f(__uint_as_float(yhi));
                e[p] = pk2(__float_as_uint(elo), __float_as_uint(ehi));
            }

            // l*mean: e . alpha'  (alpha' = l*alpha at P[6..10])
            u64 me = f2mul(e[0], P[6]);
            me = f2fma(e[1], P[7],  me);
            me = f2fma(e[2], P[8],  me);
            me = f2fma(e[3], P[9],  me);
            me = f2fma(e[4], P[10], me);

            // l2*qKq = ||W' e||^2  (W' streamed from smem, lower-tri entries 0..14)
            u64 v0 = f2mul(LW(0), e[0]);
            u64 v1 = f2fma(LW(2),  e[1], f2mul(LW(1), e[0]));
            u64 v2 = f2fma(LW(5),  e[2], f2fma(LW(4),  e[1], f2mul(LW(3),  e[0])));
            u64 v3 = f2fma(LW(9),  e[3], f2fma(LW(8),  e[2],
                     f2fma(LW(7),  e[1], f2mul(LW(6),  e[0]))));
            u64 v4 = f2fma(LW(14), e[4], f2fma(LW(13), e[3],
                     f2fma(LW(12), e[2], f2fma(LW(11), e[1], f2mul(LW(10), e[0])))));
            u64 qk = f2mul(v0, v0);
            qk = f2fma(v1, v1, qk);
            qk = f2fma(v2, v2, qk);
            qk = f2fma(v3, v3, qk);
            qk = f2fma(v4, v4, qk);

            macc[rr] = f2fma(me, r,   macc[rr]);   // s*mean = r * (l*mean)
            qacc[rr] = f2fma(qk, rsq, qacc[rr]);   // (1/d) * (l2*qKq)
        }
#undef LW
    }

#pragma unroll
    for (int rr = 0; rr < RPT; ++rr) {
        const int r = row0 + rp * RPT + rr;
        unsigned mlo, mhi, qlo, qhi;
        upk(macc[rr], mlo, mhi); upk(qacc[rr], qlo, qhi);
        g_part[(split * NROWS + r) * 8 + og] =
            make_float4(__uint_as_float(mlo), __uint_as_float(mhi),
                        __uint_as_float(qlo), __uint_as_float(qhi));
    }
}

// ---------------- reduce: combine the 6 i-splits ----------------
__global__ __launch_bounds__(256) void gp_reduce(float* __restrict__ out) {
    int idx = blockIdx.x * 256 + threadIdx.x;       // over NROWS*8
    if (idx >= NROWS * 8) return;
    float4 a0 = g_part[idx];
    float4 a1 = g_part[NROWS * 8 + idx];
    float4 a2 = g_part[2 * NROWS * 8 + idx];
    float4 a3 = g_part[3 * NROWS * 8 + idx];
    float4 a4 = g_part[4 * NROWS * 8 + idx];
    float4 a5 = g_part[5 * NROWS * 8 + idx];
    float mx = ((a0.x + a1.x) + (a2.x + a3.x)) + (a4.x + a5.x);
    float my = ((a0.y + a1.y) + (a2.y + a3.y)) + (a4.y + a5.y);
    float qz = ((a0.z + a1.z) + (a2.z + a3.z)) + (a4.z + a5.z);
    float qw = ((a0.w + a1.w) + (a2.w + a3.w)) + (a4.w + a5.w);
    reinterpret_cast<float2*>(out)[idx] = make_float2(mx, my);
    reinterpret_cast<float2*>(out + NROWS * OCH)[idx] =
        make_float2(fmaxf(72.0f - qz, 1e-6f), fmaxf(72.0f - qw, 1e-6f));
}

extern "C" void kernel_launch(void* const* d_in, const int* in_sizes, int n_in,
                              void* d_out, int out_size) {
    const float* xm  = (const float*)d_in[0];  // x_mean [8,32,32,8]
    const float* xv  = (const float*)d_in[1];  // x_var
    const float* z   = (const float*)d_in[2];  // [16,72,5]
    const float* h   = (const float*)d_in[3];  // [16,72,5]
    const float* rlp = (const float*)d_in[4];  // [16,72]
    float* out = (float*)d_out;                // [m (131072) | v (131072)]

    gp_pre<<<36, 32>>>(z, h, rlp);
    gp_main<<<dim3(NROWS / ROWSB, ISPLIT), 128>>>(xm, xv);
    gp_reduce<<<NROWS * 8 / 256, 256>>>(out);
}

// round 16
// speedup vs baseline: 1.3223x; 1.0622x over previous
#include <cuda_runtime.h>

// ---- problem constants ----
#define NROWS   8192      // N * OH * OW = 8*32*32
#define IDIM    72        // IC*KH*KW
#define OCH     16
#define NP      5
#define RKU     26        // u64 entries per record: l2, negz*5, alpha'*5, W'*15
#define RECF    52        // floats per record in global = 13 uint4
#define RECS    60        // smem float stride: og*60%32 distinct -> conflict-free
#define ROWSB   64        // rows per CTA
#define RPT     4         // rows per thread
#define ISPLIT  6
#define IQ      12        // IDIM / ISPLIT

// global param table: [i][og][RECF] floats, og = o>>1, float2-interleaved over lane=o&1
__device__ float g_params[IDIM * 8 * RECF];

typedef unsigned long long u64;

// ---------------- packed f32x2 + fast-math helpers ----------------
__device__ __forceinline__ u64 pk2(unsigned lo, unsigned hi) {
    u64 d; asm("mov.b64 %0,{%1,%2};" : "=l"(d) : "r"(lo), "r"(hi)); return d;
}
__device__ __forceinline__ void upk(u64 v, unsigned& lo, unsigned& hi) {
    asm("mov.b64 {%0,%1},%2;" : "=r"(lo), "=r"(hi) : "l"(v));
}
__device__ __forceinline__ u64 bc(float f) {
    unsigned u = __float_as_uint(f); return pk2(u, u);
}
__device__ __forceinline__ u64 f2fma(u64 a, u64 b, u64 c) {
    u64 d; asm("fma.rn.f32x2 %0,%1,%2,%3;" : "=l"(d) : "l"(a), "l"(b), "l"(c)); return d;
}
__device__ __forceinline__ u64 f2mul(u64 a, u64 b) {
    u64 d; asm("mul.rn.f32x2 %0,%1,%2;" : "=l"(d) : "l"(a), "l"(b)); return d;
}
__device__ __forceinline__ u64 f2add(u64 a, u64 b) {
    u64 d; asm("add.rn.f32x2 %0,%1,%2;" : "=l"(d) : "l"(a), "l"(b)); return d;
}
__device__ __forceinline__ float ex2f(float x) {
    float y; asm("ex2.approx.f32 %0,%1;" : "=f"(y) : "f"(x)); return y;
}
__device__ __forceinline__ float lg2f(float x) {
    float y; asm("lg2.approx.f32 %0,%1;" : "=f"(y) : "f"(x)); return y;
}
__device__ __forceinline__ float rcpf(float x) {
    float y; asm("rcp.approx.f32 %0,%1;" : "=f"(y) : "f"(x)); return y;
}

// ---------------- precompute: Cholesky solve + coalesced record store + out-init ----------------
// grid <<<9, 128>>>: block b covers i in [b*8, b*8+8), all 16 o.
__global__ __launch_bounds__(128) void gp_pre(const float* __restrict__ z,
                                              const float* __restrict__ h,
                                              const float* __restrict__ raw_l,
                                              float* __restrict__ out) {
    __shared__ __align__(16) float s_rec[8 * 8 * RECF];   // 3328 floats, packed layout

    const int tid = threadIdx.x;
    const int gid = blockIdx.x * 128 + tid;

    // ---- out-buffer init (overlaps the solve chain): mean=0, var=72 ----
    {
        const float4 z4  = make_float4(0.0f, 0.0f, 0.0f, 0.0f);
        const float4 s4  = make_float4(72.0f, 72.0f, 72.0f, 72.0f);
        float4* o4 = reinterpret_cast<float4*>(out);
        for (int idx = gid; idx < 2 * NROWS * OCH / 4; idx += 9 * 128)
            o4[idx] = (idx < NROWS * OCH / 4) ? z4 : s4;
    }

    // ---- per-neuron solve: thread = (il, o) ----
    const int o  = tid & 15;
    const int il = tid >> 4;
    const int i  = blockIdx.x * 8 + il;
    const int oi = o * IDIM + i;

    // softplus via MUFU: sp = ln2 * lg2(1 + 2^(x*log2e))
    float x   = raw_l[oi];
    float tx  = ex2f(x * 1.4426950408889634f);
    float spf = 0.6931471805599453f * lg2f(1.0f + tx);
    float l2f = spf * spf;
    float cK  = -0.7213475204444817f * rcpf(l2f);   // -log2e/(2 l2)

    float zz[NP], hf[NP];
#pragma unroll
    for (int p = 0; p < NP; ++p) {
        zz[p] = z[oi * NP + p];
        hf[p] = h[oi * NP + p];
    }

    // K in fp32 via ex2 (validated safe); fp64 copy for alpha refinement
    float  Kf[NP][NP];
    double Kd[NP][NP];
#pragma unroll
    for (int p = 0; p < NP; ++p)
#pragma unroll
        for (int q = 0; q < NP; ++q) {
            float dz = zz[p] - zz[q];
            float v = ex2f(dz * dz * cK) + (p == q ? 1e-4f : 0.0f);
            Kf[p][q] = v; Kd[p][q] = (double)v;
        }

    // fp32 Cholesky K = L L^T (rsqrt + 1 Newton)
    float L[NP][NP], rdiag[NP];
#pragma unroll
    for (int j = 0; j < NP; ++j) {
        float s = Kf[j][j];
#pragma unroll
        for (int k = 0; k < NP; ++k) if (k < j) s = fmaf(-L[j][k], L[j][k], s);
        float r = rsqrtf(s);
        r = r * fmaf(-0.5f * s * r, r, 1.5f);
        rdiag[j] = r;
        L[j][j] = s * r;
#pragma unroll
        for (int rr = 0; rr < NP; ++rr) if (rr > j) {
            float t = Kf[rr][j];
#pragma unroll
            for (int k = 0; k < NP; ++k) if (k < j) t = fmaf(-L[rr][k], L[j][k], t);
            L[rr][j] = t * r;
        }
    }
    // W = L^{-1} (lower): K^{-1} = W^T W
    float W[NP][NP];
#pragma unroll
    for (int j = 0; j < NP; ++j) {
        W[j][j] = rdiag[j];
#pragma unroll
        for (int rr = 0; rr < NP; ++rr) if (rr > j) {
            float t = 0.0f;
#pragma unroll
            for (int k = 0; k < NP; ++k) if (k >= j && k < rr) t = fmaf(L[rr][k], W[k][j], t);
            W[rr][j] = -t * rdiag[rr];
        }
    }

    // alpha0 = W^T (W h), one fp64-residual refinement
    float t1[NP], a0[NP];
#pragma unroll
    for (int p = 0; p < NP; ++p) {
        float s = 0.0f;
#pragma unroll
        for (int q = 0; q < NP; ++q) if (q <= p) s = fmaf(W[p][q], hf[q], s);
        t1[p] = s;
    }
#pragma unroll
    for (int q = 0; q < NP; ++q) {
        float s = 0.0f;
#pragma unroll
        for (int p = 0; p < NP; ++p) if (p >= q) s = fmaf(W[p][q], t1[p], s);
        a0[q] = s;
    }
    float rf[NP];
#pragma unroll
    for (int p = 0; p < NP; ++p) {
        double s = (double)hf[p];
#pragma unroll
        for (int q = 0; q < NP; ++q) s = fma(-Kd[p][q], (double)a0[q], s);
        rf[p] = (float)s;
    }
    float t2[NP], al[NP];
#pragma unroll
    for (int p = 0; p < NP; ++p) {
        float s = 0.0f;
#pragma unroll
        for (int q = 0; q < NP; ++q) if (q <= p) s = fmaf(W[p][q], rf[q], s);
        t2[p] = s;
    }
#pragma unroll
    for (int q = 0; q < NP; ++q) {
        float s = a0[q];
#pragma unroll
        for (int p = 0; p < NP; ++p) if (p >= q) s = fmaf(W[p][q], t2[p], s);
        al[q] = s;
    }

    // stage record into smem (float2-interleaved): l2, -z*5, (l*alpha)*5, (l*W)*15
    {
        float* rec = &s_rec[(il * 8 + (o >> 1)) * RECF + (o & 1)];
        rec[0] = l2f;
#pragma unroll
        for (int p = 0; p < NP; ++p) rec[(1 + p) * 2] = -zz[p];
#pragma unroll
        for (int p = 0; p < NP; ++p) rec[(6 + p) * 2] = spf * al[p];
#pragma unroll
        for (int p = 0; p < NP; ++p)
#pragma unroll
            for (int q = 0; q < NP; ++q) if (q <= p)
                rec[(11 + p * (p + 1) / 2 + q) * 2] = spf * W[p][q];
    }
    __syncthreads();

    // coalesced copy-out: block's 64 records are contiguous in g_params
    {
        float4* dst = reinterpret_cast<float4*>(g_params + blockIdx.x * 8 * 8 * RECF);
        const float4* src = reinterpret_cast<const float4*>(s_rec);
        for (int idx = tid; idx < 8 * 8 * RECF / 4; idx += 128)
            dst[idx] = src[idx];
    }
}

// ---------------- main: 6-way i-split, atomic accumulate into out (no reduce kernel) ----------------
__global__ __launch_bounds__(128) void gp_main(const float* __restrict__ xm,
                                               const float* __restrict__ xv,
                                               float* __restrict__ out) {
    __shared__ __align__(16) float2 ms_sm[IQ][ROWSB + 1];   // (mu, s2)
    __shared__ __align__(16) float  prm[IQ * 8 * RECS];

    const int tid   = threadIdx.x;
    const int row0  = blockIdx.x * ROWSB;
    const int split = blockIdx.y;
    const int i0    = split * IQ;

    // stage im2col(mu,s2) for this CTA's rows, this split's i-range
    for (int idx = tid; idx < IQ * ROWSB; idx += 128) {
        int il = idx >> 6, rlocal = idx & 63;
        int i = i0 + il;
        int c = i / 9, rem = i - c * 9;
        int kh = rem / 3, kw = rem - kh * 3;
        int r = row0 + rlocal;
        int n = r >> 10, oh = (r >> 5) & 31, ow = r & 31;
        int ih = oh + kh - 1, iw = ow + kw - 1;
        float m = 0.0f, v = 0.0f;
        if ((unsigned)ih < 32u && (unsigned)iw < 32u) {
            int g = ((n * 32 + ih) * 32 + iw) * 8 + c;
            m = xm[g]; v = xv[g];
        }
        ms_sm[il][rlocal] = make_float2(m, v);
    }
    // stage this split's param records: IQ x 8 x 13 uint4, contiguous in global
    {
        const uint4* src = reinterpret_cast<const uint4*>(g_params + i0 * 8 * RECF);
        for (int idx = tid; idx < IQ * 8 * 13; idx += 128) {
            int rrec = idx / 13, k4 = idx - rrec * 13;
            uint4 v4 = src[idx];
            *reinterpret_cast<uint4*>(&prm[rrec * RECS + 4 * k4]) = v4;
        }
    }
    __syncthreads();

    const int og = tid & 7;          // 8 o-pairs
    const int rp = tid >> 3;         // 16 row-quads -> rows rp*4 .. rp*4+3

    const u64 C_NHL2E = bc(-0.7213475204444817f);   // -0.5*log2(e)

    u64 macc[RPT] = {0ULL, 0ULL, 0ULL, 0ULL};
    u64 qacc[RPT] = {0ULL, 0ULL, 0ULL, 0ULL};

    for (int il = 0; il < IQ; ++il) {
        // record -> registers once, reused for RPT rows
        const uint4* Rq = reinterpret_cast<const uint4*>(&prm[(il * 8 + og) * RECS]);
        u64 P[RKU];
#pragma unroll
        for (int k4 = 0; k4 < 13; ++k4) {
            uint4 q = Rq[k4];
            P[2 * k4]     = pk2(q.x, q.y);
            P[2 * k4 + 1] = pk2(q.z, q.w);
        }
        const u64 l2 = P[0];

#pragma unroll
        for (int rr = 0; rr < RPT; ++rr) {
            const float2 msv = ms_sm[il][rp * RPT + rr];
            const u64 MU = bc(msv.x);
            const u64 S2 = bc(msv.y);

            // d = l2 + s2; r = 1/sqrt(d) via MUFU per half
            u64 d = f2add(l2, S2);
            unsigned dlo, dhi; upk(d, dlo, dhi);
            float rlo = rsqrtf(__uint_as_float(dlo));
            float rhi = rsqrtf(__uint_as_float(dhi));
            u64 r   = pk2(__float_as_uint(rlo), __float_as_uint(rhi));
            u64 rsq = f2mul(r, r);                   // 1/d
            const u64 ccp = f2mul(rsq, C_NHL2E);     // -log2e/(2d)

            // e_p = 2^( ccp*(mu-z_p)^2 ) via MUFU EX2 per half
            u64 e[NP];
#pragma unroll
            for (int p = 0; p < NP; ++p) {
                u64 t  = f2add(MU, P[1 + p]);        // P holds -z
                u64 t2 = f2mul(t, t);
                u64 y  = f2mul(t2, ccp);
                unsigned ylo, yhi; upk(y, ylo, yhi);
                float elo = ex2f(__uint_as_float(ylo));
                float ehi = ex2f(__uint_as_float(yhi));
                e[p] = pk2(__float_as_uint(elo), __float_as_uint(ehi));
            }

            // l*mean: e . alpha'  (alpha' = l*alpha at P[6..10])
            u64 me = f2mul(e[0], P[6]);
            me = f2fma(e[1], P[7],  me);
            me = f2fma(e[2], P[8],  me);
            me = f2fma(e[3], P[9],  me);
            me = f2fma(e[4], P[10], me);

            // l2*qKq = ||W' e||^2  (W' = l*W lower-tri at P[11..25])
            u64 v0 = f2mul(P[11], e[0]);
            u64 v1 = f2fma(P[13], e[1], f2mul(P[12], e[0]));
            u64 v2 = f2fma(P[16], e[2], f2fma(P[15], e[1], f2mul(P[14], e[0])));
            u64 v3 = f2fma(P[20], e[3], f2fma(P[19], e[2],
                     f2fma(P[18], e[1], f2mul(P[17], e[0]))));
            u64 v4 = f2fma(P[25], e[4], f2fma(P[24], e[3],
                     f2fma(P[23], e[2], f2fma(P[22], e[1], f2mul(P[21], e[0])))));
            u64 qk = f2mul(v0, v0);
            qk = f2fma(v1, v1, qk);
            qk = f2fma(v2, v2, qk);
            qk = f2fma(v3, v3, qk);
            qk = f2fma(v4, v4, qk);

            macc[rr] = f2fma(me, r,   macc[rr]);   // s*mean = r * (l*mean)
            qacc[rr] = f2fma(qk, rsq, qacc[rr]);   // (1/d) * (l2*qKq)
        }
    }

    // ---- accumulate directly into out (mean += m; var(init 72) += -q) ----
#pragma unroll
    for (int rr = 0; rr < RPT; ++rr) {
        const int r = row0 + rp * RPT + rr;
        unsigned mlo, mhi, qlo, qhi;
        upk(macc[rr], mlo, mhi); upk(qacc[rr], qlo, qhi);
        const int base = (r * 8 + og) * 2;
        atomicAdd(&out[base],     __uint_as_float(mlo));
        atomicAdd(&out[base + 1], __uint_as_float(mhi));
        atomicAdd(&out[NROWS * OCH + base],     -__uint_as_float(qlo));
        atomicAdd(&out[NROWS * OCH + base + 1], -__uint_as_float(qhi));
    }
}

extern "C" void kernel_launch(void* const* d_in, const int* in_sizes, int n_in,
                              void* d_out, int out_size) {
    const float* xm  = (const float*)d_in[0];  // x_mean [8,32,32,8]
    const float* xv  = (const float*)d_in[1];  // x_var
    const float* z   = (const float*)d_in[2];  // [16,72,5]
    const float* h   = (const float*)d_in[3];  // [16,72,5]
    const float* rlp = (const float*)d_in[4];  // [16,72]
    float* out = (float*)d_out;                // [m (131072) | v (131072)]

    gp_pre<<<9, 128>>>(z, h, rlp, out);
    gp_main<<<dim3(NROWS / ROWSB, ISPLIT), 128>>>(xm, xv, out);
}